// round 3
// baseline (speedup 1.0000x reference)
#include <cuda_runtime.h>

// SimilarityMeasureModel on GB300 (sm_103a).
// Inputs: x, y [B=32, P=3, C=512, N=1024] f32 (N contiguous).
// Per (b,p,n): l1 = sum_c |x-y|, l2 = sum_c (x-y)^2 ; out = [l1,l2,l1] interleaved.
//
// R3: 768 blocks (2x R2), each covering 128 n-values with C split 8 ways.
// 608 blocks resident (4/SM x 152 SMs) + 160 dynamically backfilled ->
// tail smoothing + higher occupancy / bytes-in-flight.

static constexpr int B = 32;
static constexpr int P = 3;
static constexpr int C = 512;
static constexpr int N = 1024;
static constexpr int N4 = N / 4;            // 256 float4 per row
static constexpr int SEGS = 8;              // C split
static constexpr int CSEG = C / SEGS;       // 64
static constexpr int NV_PER_BLK = 32;       // float4 per block -> 128 n values
static constexpr int NCHUNKS = N4 / NV_PER_BLK;              // 8
static constexpr int BLOCKS = B * P * NCHUNKS;               // 768

__global__ void __launch_bounds__(256, 4)
sim_measure_kernel(const float4* __restrict__ x,
                   const float4* __restrict__ y,
                   float* __restrict__ out) {
    const int bid = blockIdx.x;
    const int bp  = bid >> 3;                 // 0..95  (b*P + p)
    const int nq  = bid & 7;                  // which 128-n chunk

    const int tid = threadIdx.x;
    const int s   = tid >> 5;                 // C-segment 0..7 (1 warp each)
    const int n4  = tid & 31;                 // float4 index within chunk

    const int n4g = nq * NV_PER_BLK + n4;     // float4 col within row
    size_t idx = ((size_t)bp * C + (size_t)s * CSEG) * N4 + n4g;

    float4 l1 = make_float4(0.f, 0.f, 0.f, 0.f);
    float4 l2 = make_float4(0.f, 0.f, 0.f, 0.f);

    #pragma unroll 4
    for (int c = 0; c < CSEG; ++c) {
        float4 a = __ldg(x + idx);
        float4 b = __ldg(y + idx);
        idx += N4;
        float d0 = a.x - b.x, d1 = a.y - b.y, d2 = a.z - b.z, d3 = a.w - b.w;
        l1.x += fabsf(d0); l1.y += fabsf(d1); l1.z += fabsf(d2); l1.w += fabsf(d3);
        l2.x = fmaf(d0, d0, l2.x); l2.y = fmaf(d1, d1, l2.y);
        l2.z = fmaf(d2, d2, l2.z); l2.w = fmaf(d3, d3, l2.w);
    }

    // Combine the 8 C-segments through shared memory.
    __shared__ float4 sL1[SEGS][NV_PER_BLK];
    __shared__ float4 sL2[SEGS][NV_PER_BLK];
    sL1[s][n4] = l1;
    sL2[s][n4] = l2;
    __syncthreads();

    // 128 n-values per block: threads 0..127 each finalize one n.
    if (tid < 128) {
        const int m4 = tid >> 2;    // which float4 group (0..31)
        const int j  = tid & 3;     // component

        float a1 = 0.f, a2 = 0.f;
        #pragma unroll
        for (int ss = 0; ss < SEGS; ++ss) {
            const float* p1 = (const float*)&sL1[ss][m4];
            const float* p2 = (const float*)&sL2[ss][m4];
            a1 += p1[j];
            a2 += p2[j];
        }

        // pair = bp*N + nq*128 + tid ; out layout [l1, l2, l1] per pair
        const size_t pair = (size_t)bp * N + (size_t)nq * 128 + tid;
        const size_t o = pair * 3;
        out[o + 0] = a1;
        out[o + 1] = a2;
        out[o + 2] = a1;
    }
}

extern "C" void kernel_launch(void* const* d_in, const int* in_sizes, int n_in,
                              void* d_out, int out_size) {
    const float4* x = (const float4*)d_in[0];
    const float4* y = (const float4*)d_in[1];
    float* out = (float*)d_out;

    sim_measure_kernel<<<BLOCKS, 256>>>(x, y, out);
}